// round 12
// baseline (speedup 1.0000x reference)
#include <cuda_runtime.h>

// Problem constants: N=1024, DIM=201, G=200, R=72, C=4
#define NIMG 1024
#define DIMV 201
#define GG   200
#define RR   72
#define CC   4
#define RC   288    // R*C floats per channel (contiguous)
#define NIT  25     // iterations; each covers 4 channels from TWO streams (8 total)
#define HOFF 7200   // 100 channels * 72 float4 = offset of stream B

// Scratch (device globals: allocation-free, graph-safe).
__device__ float        g_loss[NIMG];
__device__ unsigned int g_count = 0;   // reset by last block each run

// One block per image, 288 threads, 7 blocks/SM -> all 1024 blocks in ONE wave.
// Two independent channel streams per thread (A: ch 0..99, B: ch 100..199),
// interleaved in one loop -> 2 LDG.128 in flight per thread structurally.
// Thread t: float4 index i*288+t -> channel 4i + t/72 (A) / +100 (B),
// slots 4(t%72)..+3. Warp 0 parses labels via ballots in the head (no barrier).
__global__ __launch_bounds__(RC, 7) void lane_loss_kernel(
    const float* __restrict__ x, const int* __restrict__ labels,
    float* __restrict__ out)
{
    __shared__ float sS[CC][RC];           // partial sum(exp) per residue q
    __shared__ float sP[CC][RC];           // partial sum(w*exp) per residue q
    __shared__ float s_pos[RC];            // row-major: s_pos[r*4+c]
    __shared__ int   s_top[CC];
    __shared__ int   s_down[CC];
    __shared__ bool  s_last;

    const int n   = blockIdx.x;
    const int tid = threadIdx.x;
    const int q   = tid / 72;         // channel residue class 0..3
    const int m   = tid % 72;         // float4 slot group 0..71

    // ---- head: warp 0 loads all labels + parses top/down (no barrier) ----
    if (tid < 32) {
        const int* lp = labels + (size_t)n * RC;
        unsigned bal[9];
        #pragma unroll
        for (int j = 0; j < 9; ++j)
            bal[j] = __ballot_sync(0xffffffffu, lp[j * 32 + tid] < GG);

        if (tid < CC) {
            // 72-bit validity mask for column tid: row 8w+k <- ballot w bit (4k+tid)
            unsigned long long lo = 0ull;   // rows 0..63
            unsigned hi = 0u;               // rows 64..71
            #pragma unroll
            for (int w = 0; w < 8; ++w) {
                #pragma unroll
                for (int k = 0; k < 8; ++k)
                    lo |= (unsigned long long)((bal[w] >> (4 * k + tid)) & 1u)
                          << (8 * w + k);
            }
            #pragma unroll
            for (int k = 0; k < 8; ++k)
                hi |= ((bal[8] >> (4 * k + tid)) & 1u) << k;

            const bool any = (lo | (unsigned long long)hi) != 0ull;
            int top;
            if (lo)      top = __ffsll((long long)lo) - 1;
            else if (hi) top = 64 + __ffs(hi) - 1;
            else         top = 0;

            // trans[r] = v[r] & !v[r+1], r in [0,70]
            unsigned long long sv  = (lo >> 1) | ((unsigned long long)(hi & 1u) << 63);
            unsigned long long tlo = lo & ~sv;
            unsigned           thi = hi & ~(hi >> 1) & 0x7Fu;
            int first_trans;
            const bool any_trans = (tlo != 0ull) || (thi != 0u);
            if (tlo)      first_trans = __ffsll((long long)tlo) - 1;
            else if (thi) first_trans = 64 + __ffs(thi) - 1;
            else          first_trans = 0;

            const bool v0    = (lo & 1ull) != 0ull;
            const bool v1    = ((lo >> 1) & 1ull) != 0ull;
            const bool vlast = ((hi >> 7) & 1u) != 0u;
            int down = (v0 && !v1) ? 0
                     : (vlast ? (RR - 1)
                     : (any_trans ? first_trans : 0));
            if (!any) { top = 0; down = 0; }
            s_top[tid]  = top;
            s_down[tid] = down;
        }
    }

    // ---- Phase 1: dual-stream exp accumulation (MLP=2 structurally) ----
    {
        const float4* xp = (const float4*)x + (size_t)n * (DIMV * 72) + tid;
        float s0 = 0.f, s1 = 0.f, s2 = 0.f, s3 = 0.f;
        float p0 = 0.f, p1 = 0.f, p2 = 0.f, p3 = 0.f;

        #pragma unroll
        for (int i = 0; i < NIT; ++i) {
            float4 a = xp[i * 288];            // stream A: channels 4i+q
            float4 b = xp[i * 288 + HOFF];     // stream B: channels 100+4i+q
            const float wa = (float)(4 * i);         // FFMA immediates
            const float wb = (float)(4 * i + 100);

            float a0 = __expf(a.x), a1 = __expf(a.y);
            float a2 = __expf(a.z), a3 = __expf(a.w);
            float b0 = __expf(b.x), b1 = __expf(b.y);
            float b2 = __expf(b.z), b3 = __expf(b.w);

            s0 += a0 + b0;  p0 = fmaf(a0, wa, p0);  p0 = fmaf(b0, wb, p0);
            s1 += a1 + b1;  p1 = fmaf(a1, wa, p1);  p1 = fmaf(b1, wb, p1);
            s2 += a2 + b2;  p2 = fmaf(a2, wa, p2);  p2 = fmaf(b2, wb, p2);
            s3 += a3 + b3;  p3 = fmaf(a3, wa, p3);  p3 = fmaf(b3, wb, p3);
        }
        // fold in channel residue: true weight = (4i [+100]) + q
        const float fq = (float)q;
        p0 = fmaf(fq, s0, p0);
        p1 = fmaf(fq, s1, p1);
        p2 = fmaf(fq, s2, p2);
        p3 = fmaf(fq, s3, p3);

        const int base = m * 4;
        sS[q][base + 0] = s0;  sP[q][base + 0] = p0;
        sS[q][base + 1] = s1;  sP[q][base + 1] = p1;
        sS[q][base + 2] = s2;  sP[q][base + 2] = p2;
        sS[q][base + 3] = s3;  sP[q][base + 3] = p3;
    }
    __syncthreads();

    // ---- combine residue partials -> pos ----
    {
        float s = sS[0][tid] + sS[1][tid] + sS[2][tid] + sS[3][tid];
        float p = sP[0][tid] + sP[1][tid] + sP[2][tid] + sP[3][tid];
        s_pos[tid] = __fdividef(p, s);
    }
    __syncthreads();

    // ---- per-image loss: parallel over warp 0 ----
    if (tid < 32) {
        const int tl = max(s_top[0],  max(s_top[1],  s_top[2]));
        const int dl = min(s_down[0], min(s_down[1], s_down[2]));
        const int tr = max(s_top[1],  max(s_top[2],  s_top[3]));
        const int dr = min(s_down[1], min(s_down[2], s_down[3]));
        const bool al = (tl < dl);
        const bool ar = (tr < dr);

        float suml = 0.0f, sumr = 0.0f;
        const float4* pos4 = (const float4*)s_pos;
        #pragma unroll
        for (int k = 0; k < 3; ++k) {
            int r = tid + k * 32;
            if (r < RR) {
                float4 qv = pos4[r];
                float ddl = fabsf(qv.x - 2.0f * qv.y + qv.z);
                float ddr = fabsf(qv.y - 2.0f * qv.z + qv.w);
                if (r >= tl && r <= dl) suml += ddl;
                if (r >= tr && r <= dr) sumr += ddr;
            }
        }
        #pragma unroll
        for (int o = 16; o > 0; o >>= 1) {
            suml += __shfl_down_sync(0xffffffffu, suml, o);
            sumr += __shfl_down_sync(0xffffffffu, sumr, o);
        }
        if (tid == 0) {
            float contrib = 0.0f;
            if (al) contrib += suml / (float)(dl - tl + 1);
            if (ar) contrib += sumr / (float)(dr - tr + 1);
            float denom = (al && ar) ? (2.0f * (float)RR) : (float)RR;
            g_loss[n] = contrib / denom;

            __threadfence();
            unsigned int old = atomicAdd(&g_count, 1u);
            s_last = (old == NIMG - 1);
        }
    }
    __syncthreads();

    // ---- last block: deterministic fixed-order global reduction ----
    if (s_last) {
        float sum = 0.0f;
        int   cnt = 0;
        #pragma unroll
        for (int k = 0; k < 4; ++k) {
            int i = tid + k * RC;            // covers 0..1151
            if (i < NIMG) {
                float v = g_loss[i];
                sum += v;
                cnt += (v != 0.0f) ? 1 : 0;
            }
        }
        #pragma unroll
        for (int o = 16; o > 0; o >>= 1) {
            sum += __shfl_down_sync(0xffffffffu, sum, o);
            cnt += __shfl_down_sync(0xffffffffu, cnt, o);
        }
        __shared__ float wsum[9];
        __shared__ int   wcnt[9];
        const int wid = tid >> 5, lid = tid & 31;
        if (lid == 0) { wsum[wid] = sum; wcnt[wid] = cnt; }
        __syncthreads();
        if (tid == 0) {
            float ts = 0.0f; int tc = 0;
            #pragma unroll
            for (int w = 0; w < 9; ++w) { ts += wsum[w]; tc += wcnt[w]; }
            out[0] = (tc > 0) ? (ts / (float)tc) : 0.0f;
            g_count = 0;   // reset for next graph replay
        }
    }
}

extern "C" void kernel_launch(void* const* d_in, const int* in_sizes, int n_in,
                              void* d_out, int out_size)
{
    const float* x      = (const float*)d_in[0];   // [1024, 201, 72, 4] f32
    const int*   labels = (const int*)d_in[1];     // [1024, 72, 4] int32
    float*       out    = (float*)d_out;           // scalar f32

    lane_loss_kernel<<<NIMG, RC>>>(x, labels, out);
}